// round 3
// baseline (speedup 1.0000x reference)
#include <cuda_runtime.h>
#include <math.h>

// Problem constants
#define BATCH   65536
#define NNODES  2
#define FIN     256
#define NHEADS  4
#define DHID    256
#define KDIM    1024            // NHEADS * DHID
#define MROWS   131072          // BATCH * NNODES
#define SLOPE   0.2f

// Scratch (static __device__, allocation-free)
__device__ float g_wst[FIN * 8];            // [f][c], c<4: src head c, c>=4: tgt head c-4
__device__ float g_coef[BATCH * 16];        // [b][i][head][j], premultiplied by 0.25

// ---------------------------------------------------------------------------
// Kernel 1: ws[f][h] = sum_d W[f, h*256+d] * a[h, d]  (src) / a[h, 256+d] (tgt)
// 2048 threads, one dot of length 256 each.
// ---------------------------------------------------------------------------
__global__ void gat_prep(const float* __restrict__ W, const float* __restrict__ a) {
    int t = blockIdx.x * blockDim.x + threadIdx.x;   // 0..2047
    if (t >= FIN * 8) return;
    int f   = t >> 3;
    int c   = t & 7;
    int hd  = c & 3;
    int tg  = c >> 2;                                // 0 = src, 1 = tgt
    const float4* wrow = (const float4*)(W + f * KDIM + hd * DHID);
    const float4* av   = (const float4*)(a + hd * (2 * DHID) + tg * DHID);
    float s = 0.f;
#pragma unroll 8
    for (int d = 0; d < DHID / 4; ++d) {
        float4 w4 = wrow[d];
        float4 a4 = av[d];
        s += w4.x * a4.x + w4.y * a4.y + w4.z * a4.z + w4.w * a4.w;
    }
    g_wst[f * 8 + c] = s;
}

// ---------------------------------------------------------------------------
// Kernel 2: attention coefficients. One warp per graph b.
// p[n*8 + c]: c<4 src[n][hd], c>=4 tgt[n][hd]
// ---------------------------------------------------------------------------
__device__ __forceinline__ float lrelu(float x) { return x > 0.f ? x : SLOPE * x; }

__global__ void gat_attn(const float* __restrict__ h, const int* __restrict__ adj) {
    int warp = threadIdx.x >> 5;
    int lane = threadIdx.x & 31;
    int b = blockIdx.x * 8 + warp;
    const float* hb = h + (size_t)b * (NNODES * FIN);

    float p[16];
#pragma unroll
    for (int c = 0; c < 16; ++c) p[c] = 0.f;

#pragma unroll
    for (int q = 0; q < 8; ++q) {
        int f = lane + q * 32;
        float h0 = hb[f];
        float h1 = hb[FIN + f];
        const float4* wp = (const float4*)(g_wst + f * 8);
        float4 w0 = wp[0];
        float4 w1 = wp[1];
        p[0] += h0 * w0.x; p[1] += h0 * w0.y; p[2] += h0 * w0.z; p[3] += h0 * w0.w;
        p[4] += h0 * w1.x; p[5] += h0 * w1.y; p[6] += h0 * w1.z; p[7] += h0 * w1.w;
        p[8]  += h1 * w0.x; p[9]  += h1 * w0.y; p[10] += h1 * w0.z; p[11] += h1 * w0.w;
        p[12] += h1 * w1.x; p[13] += h1 * w1.y; p[14] += h1 * w1.z; p[15] += h1 * w1.w;
    }
#pragma unroll
    for (int off = 16; off > 0; off >>= 1) {
#pragma unroll
        for (int c = 0; c < 16; ++c)
            p[c] += __shfl_xor_sync(0xFFFFFFFFu, p[c], off);
    }

    if (lane == 0) {
        int a00 = adj[b * 4 + 0];
        int a01 = adj[b * 4 + 1];
        int a10 = adj[b * 4 + 2];
        int a11 = adj[b * 4 + 3];
        float4 res[4];
        float* cf = (float*)res;
#pragma unroll
        for (int i = 0; i < 2; ++i) {
            int m0 = (i == 0) ? a00 : a10;
            int m1 = (i == 0) ? a01 : a11;
#pragma unroll
            for (int hd = 0; hd < 4; ++hd) {
                float si = p[i * 8 + hd];
                float e0 = lrelu(si + p[0 * 8 + 4 + hd]);
                float e1 = lrelu(si + p[1 * 8 + 4 + hd]);
                float mx = -INFINITY;
                if (m0) mx = e0;
                if (m1) mx = fmaxf(mx, e1);
                float x0 = m0 ? expf(e0 - mx) : 0.f;
                float x1 = m1 ? expf(e1 - mx) : 0.f;
                float inv = 0.25f / (x0 + x1);   // fold mean over heads (/4)
                cf[i * 8 + hd * 2 + 0] = x0 * inv;
                cf[i * 8 + hd * 2 + 1] = x1 * inv;
            }
        }
        float4* dst = (float4*)(g_coef + (size_t)b * 16);
        dst[0] = res[0]; dst[1] = res[1]; dst[2] = res[2]; dst[3] = res[3];
    }
}

// ---------------------------------------------------------------------------
// Kernel 3: out(131072 x 256) = Hm(131072 x 1024) @ Wstack(1024 x 256)
//   Hm[row, h*256+f] = c0[row,h]*h[b,0,f] + c1[row,h]*h[b,1,f]   (built on the fly)
//   Wstack[h*256+f, d] = W[f, h*256+d]                           (indexed directly)
// 128x128 CTA tile, BK=16, 8x8 register tile per thread (256 threads).
// ---------------------------------------------------------------------------
#define BM 128
#define BN 128
#define BK 16

__global__ void __launch_bounds__(256, 2)
gat_main(const float* __restrict__ h, const float* __restrict__ W,
         float* __restrict__ out) {
    __shared__ float As[BK][BM + 4];
    __shared__ float Bs[BK][BN];

    const int m0 = blockIdx.x * BM;
    const int n0 = blockIdx.y * BN;
    const int tid = threadIdx.x;
    const int tx = tid & 15;         // n-tile index
    const int ty = tid >> 4;         // m-tile index

    // A-construction mapping: this thread builds rows k = akh*8 + g*4 + j for column am
    const int am  = tid & 127;
    const int akh = tid >> 7;        // 0 or 1
    const int row = m0 + am;
    const long hbase = (long)(row >> 1) * (NNODES * FIN);
    const float* hp0 = h + hbase;          // h[b,0,:]
    const float* hp1 = h + hbase + FIN;    // h[b,1,:]

    float acc[8][8];
#pragma unroll
    for (int i = 0; i < 8; ++i)
#pragma unroll
        for (int j = 0; j < 8; ++j) acc[i][j] = 0.f;

    float c0 = 0.f, c1 = 0.f;

    for (int kc = 0; kc < KDIM / BK; ++kc) {
        const int k0 = kc * BK;
        if ((k0 & 255) == 0) {                  // new head every 16 chunks
            int hd = k0 >> 8;
            c0 = g_coef[(size_t)row * 8 + hd * 2 + 0];
            c1 = g_coef[(size_t)row * 8 + hd * 2 + 1];
        }

        // ---- gmem -> regs: A fragment (constructed) ----
        float areg[2][4];
#pragma unroll
        for (int g = 0; g < 2; ++g) {
            int k4 = akh * 8 + g * 4;
            int fb = (k0 + k4) & 255;
            float4 v0 = *(const float4*)(hp0 + fb);
            float4 v1 = *(const float4*)(hp1 + fb);
            areg[g][0] = c0 * v0.x + c1 * v1.x;
            areg[g][1] = c0 * v0.y + c1 * v1.y;
            areg[g][2] = c0 * v0.z + c1 * v1.z;
            areg[g][3] = c0 * v0.w + c1 * v1.w;
        }
        // ---- gmem -> regs: B fragment (Wstack indexed from W) ----
        float4 breg[2];
        int bk[2], bn[2];
#pragma unroll
        for (int ld = 0; ld < 2; ++ld) {
            int v = tid + 256 * ld;             // 0..511
            bk[ld] = v >> 5;                    // 0..15
            bn[ld] = (v & 31) * 4;              // 0..124
            int kk = k0 + bk[ld];
            int f = kk & 255, hh = kk >> 8;
            breg[ld] = *(const float4*)(W + (size_t)f * KDIM + hh * DHID + n0 + bn[ld]);
        }

        __syncthreads();
#pragma unroll
        for (int g = 0; g < 2; ++g) {
            int k4 = akh * 8 + g * 4;
            As[k4 + 0][am] = areg[g][0];
            As[k4 + 1][am] = areg[g][1];
            As[k4 + 2][am] = areg[g][2];
            As[k4 + 3][am] = areg[g][3];
        }
#pragma unroll
        for (int ld = 0; ld < 2; ++ld)
            *(float4*)&Bs[bk[ld]][bn[ld]] = breg[ld];
        __syncthreads();

        // ---- compute ----
#pragma unroll
        for (int k = 0; k < BK; ++k) {
            float af[8], bf[8];
            float4 a0 = *(const float4*)&As[k][ty * 8];
            float4 a1 = *(const float4*)&As[k][ty * 8 + 4];
            float4 b0 = *(const float4*)&Bs[k][tx * 8];
            float4 b1 = *(const float4*)&Bs[k][tx * 8 + 4];
            af[0]=a0.x; af[1]=a0.y; af[2]=a0.z; af[3]=a0.w;
            af[4]=a1.x; af[5]=a1.y; af[6]=a1.z; af[7]=a1.w;
            bf[0]=b0.x; bf[1]=b0.y; bf[2]=b0.z; bf[3]=b0.w;
            bf[4]=b1.x; bf[5]=b1.y; bf[6]=b1.z; bf[7]=b1.w;
#pragma unroll
            for (int i = 0; i < 8; ++i)
#pragma unroll
                for (int j = 0; j < 8; ++j)
                    acc[i][j] += af[i] * bf[j];
        }
    }

    // ---- epilogue: out[row, n] ----
#pragma unroll
    for (int i = 0; i < 8; ++i) {
        long orow = (long)(m0 + ty * 8 + i) * 256 + n0 + tx * 8;
        *(float4*)(out + orow)     = make_float4(acc[i][0], acc[i][1], acc[i][2], acc[i][3]);
        *(float4*)(out + orow + 4) = make_float4(acc[i][4], acc[i][5], acc[i][6], acc[i][7]);
    }
}

// ---------------------------------------------------------------------------
// Launch
// ---------------------------------------------------------------------------
extern "C" void kernel_launch(void* const* d_in, const int* in_sizes, int n_in,
                              void* d_out, int out_size) {
    const float* h   = (const float*)d_in[0];   // (65536, 2, 256) f32
    const int*   adj = (const int*)  d_in[1];   // (65536, 1, 2, 2) i32
    const float* W   = (const float*)d_in[2];   // (256, 1024) f32
    const float* a   = (const float*)d_in[3];   // (4, 512, 1) f32
    float* out = (float*)d_out;                 // (65536, 2, 256) f32

    gat_prep<<<8, 256>>>(W, a);
    gat_attn<<<BATCH / 8, 256>>>(h, adj);
    gat_main<<<dim3(MROWS / BM, 256 / BN), 256>>>(h, W, out);
}

// round 5
// speedup vs baseline: 2.0733x; 2.0733x over previous
#include <cuda_runtime.h>
#include <cuda_bf16.h>
#include <math.h>
#include <stdint.h>

// Problem constants
#define BATCH   65536
#define NNODES  2
#define FIN     256
#define KDIM    1024
#define MROWS   131072
#define SLOPE   0.2f

// GEMM tiling
#define BM 128
#define BN 128
#define BK 32
#define NKITER 32               // 1024 / 32

// SMEM layout (bytes)
#define HOFF   0                // h cache: 64 graphs * 512 f32 = 131072
#define AOFF   131072           // A bufs: 2 * (hi 10240 + lo 10240)
#define ABUFS  20480
#define BOFF   172032           // B bufs: 2 * (hi 10240 + lo 10240)
#define BBUFS  20480
#define SMEM_TOTAL 212992
#define PITCH  80               // 40 halves per row (32 used + 8 pad)

// Scratch
__device__ float g_wst[FIN * 8];
__device__ float g_coef[BATCH * 16];       // [b][i][head][j] * 0.25
__device__ uint4 g_Whi4[256 * 1024 / 8];   // Wstack^T hi, [n][k] bf16, k contiguous
__device__ uint4 g_Wlo4[256 * 1024 / 8];   // Wstack^T lo

// ---------------------------------------------------------------------------
// PTX helpers (all plain sm_80-era instructions; no 'a'-gated features)
// ---------------------------------------------------------------------------
__device__ __forceinline__ uint32_t smem_u32(const void* p) {
    uint32_t a;
    asm("{ .reg .u64 t; cvta.to.shared.u64 t, %1; cvt.u32.u64 %0, t; }" : "=r"(a) : "l"(p));
    return a;
}
__device__ __forceinline__ void ldsm_x4(uint32_t* r, uint32_t addr) {
    asm volatile("ldmatrix.sync.aligned.m8n8.x4.shared.b16 {%0,%1,%2,%3}, [%4];"
        : "=r"(r[0]), "=r"(r[1]), "=r"(r[2]), "=r"(r[3]) : "r"(addr));
}
__device__ __forceinline__ void ldsm_x2(uint32_t* r, uint32_t addr) {
    asm volatile("ldmatrix.sync.aligned.m8n8.x2.shared.b16 {%0,%1}, [%2];"
        : "=r"(r[0]), "=r"(r[1]) : "r"(addr));
}
__device__ __forceinline__ void mma_bf16(float* d, const uint32_t* a, const uint32_t* b) {
    asm volatile("mma.sync.aligned.m16n8k16.row.col.f32.bf16.bf16.f32 "
        "{%0,%1,%2,%3}, {%4,%5,%6,%7}, {%8,%9}, {%0,%1,%2,%3};"
        : "+f"(d[0]), "+f"(d[1]), "+f"(d[2]), "+f"(d[3])
        : "r"(a[0]), "r"(a[1]), "r"(a[2]), "r"(a[3]), "r"(b[0]), "r"(b[1]));
}

// ---------------------------------------------------------------------------
// Kernel 1: wst dot products. One warp per output, 2048 outputs.
// ---------------------------------------------------------------------------
__global__ void gat_prep(const float* __restrict__ W, const float* __restrict__ a) {
    int wid = threadIdx.x >> 5, lane = threadIdx.x & 31;
    int t = blockIdx.x * 8 + wid;                    // t = f*8 + c
    int f = t >> 3, c = t & 7, hd = c & 3, tg = c >> 2;
    const float4* wrow = (const float4*)(W + f * KDIM + hd * 256);
    const float4* av   = (const float4*)(a + hd * 512 + tg * 256);
    float s = 0.f;
#pragma unroll
    for (int q = 0; q < 2; ++q) {
        int i = lane + q * 32;
        float4 w4 = wrow[i], a4 = av[i];
        s += w4.x * a4.x + w4.y * a4.y + w4.z * a4.z + w4.w * a4.w;
    }
#pragma unroll
    for (int off = 16; off > 0; off >>= 1) s += __shfl_xor_sync(0xFFFFFFFFu, s, off);
    if (lane == 0) g_wst[t] = s;
}

// ---------------------------------------------------------------------------
// Kernel 1b: split Wstack^T into bf16 hi/lo. Wt[n][k] = W[k&255][(k>>8)*256+n]
// ---------------------------------------------------------------------------
__global__ void gat_prepB(const float* __restrict__ W) {
    int idx = blockIdx.x * 256 + threadIdx.x;        // n*1024 + k
    int n = idx >> 10, k = idx & 1023;
    int f = k & 255, hd = k >> 8;
    float w = W[f * KDIM + hd * 256 + n];
    __nv_bfloat16 hi = __float2bfloat16(w);
    __nv_bfloat16 lo = __float2bfloat16(w - __bfloat162float(hi));
    ((__nv_bfloat16*)g_Whi4)[idx] = hi;
    ((__nv_bfloat16*)g_Wlo4)[idx] = lo;
}

// ---------------------------------------------------------------------------
// Kernel 2: attention coefficients (unchanged; passed R3).
// ---------------------------------------------------------------------------
__device__ __forceinline__ float lrelu(float x) { return x > 0.f ? x : SLOPE * x; }

__global__ void gat_attn(const float* __restrict__ h, const int* __restrict__ adj) {
    int warp = threadIdx.x >> 5;
    int lane = threadIdx.x & 31;
    int b = blockIdx.x * 8 + warp;
    const float* hb = h + (size_t)b * (NNODES * FIN);

    float p[16];
#pragma unroll
    for (int c = 0; c < 16; ++c) p[c] = 0.f;
#pragma unroll
    for (int q = 0; q < 8; ++q) {
        int f = lane + q * 32;
        float h0 = hb[f];
        float h1 = hb[FIN + f];
        const float4* wp = (const float4*)(g_wst + f * 8);
        float4 w0 = wp[0];
        float4 w1 = wp[1];
        p[0] += h0 * w0.x; p[1] += h0 * w0.y; p[2] += h0 * w0.z; p[3] += h0 * w0.w;
        p[4] += h0 * w1.x; p[5] += h0 * w1.y; p[6] += h0 * w1.z; p[7] += h0 * w1.w;
        p[8]  += h1 * w0.x; p[9]  += h1 * w0.y; p[10] += h1 * w0.z; p[11] += h1 * w0.w;
        p[12] += h1 * w1.x; p[13] += h1 * w1.y; p[14] += h1 * w1.z; p[15] += h1 * w1.w;
    }
#pragma unroll
    for (int off = 16; off > 0; off >>= 1) {
#pragma unroll
        for (int c = 0; c < 16; ++c) p[c] += __shfl_xor_sync(0xFFFFFFFFu, p[c], off);
    }
    if (lane == 0) {
        int a00 = adj[b * 4 + 0], a01 = adj[b * 4 + 1];
        int a10 = adj[b * 4 + 2], a11 = adj[b * 4 + 3];
        float4 res[4];
        float* cf = (float*)res;
#pragma unroll
        for (int i = 0; i < 2; ++i) {
            int m0 = (i == 0) ? a00 : a10;
            int m1 = (i == 0) ? a01 : a11;
#pragma unroll
            for (int hd = 0; hd < 4; ++hd) {
                float si = p[i * 8 + hd];
                float e0 = lrelu(si + p[4 + hd]);
                float e1 = lrelu(si + p[12 + hd]);
                float mx = -INFINITY;
                if (m0) mx = e0;
                if (m1) mx = fmaxf(mx, e1);
                float x0 = m0 ? expf(e0 - mx) : 0.f;
                float x1 = m1 ? expf(e1 - mx) : 0.f;
                float inv = 0.25f / (x0 + x1);
                cf[i * 8 + hd * 2 + 0] = x0 * inv;
                cf[i * 8 + hd * 2 + 1] = x1 * inv;
            }
        }
        float4* dst = (float4*)(g_coef + (size_t)b * 16);
        dst[0] = res[0]; dst[1] = res[1]; dst[2] = res[2]; dst[3] = res[3];
    }
}

// ---------------------------------------------------------------------------
// Kernel 3: mma.sync bf16 3-split GEMM with fused A construction.
// grid (2, 1024): x = n-block (fast -> L2 h reuse), y = m-block.
// ---------------------------------------------------------------------------
__global__ void __launch_bounds__(256, 1)
gat_main(const float* __restrict__ h, float* __restrict__ out) {
    extern __shared__ char smem[];
    const uint32_t sb = smem_u32(smem);
    const int tid = threadIdx.x;
    const int wid = tid >> 5;
    const int lane = tid & 31;
    const int m0 = blockIdx.y * BM;
    const int n0g = blockIdx.x * BN;

    // ---- prologue: copy h tile (64 graphs * 512 f32, contiguous) ----
    {
        const uint4* src = (const uint4*)(h + (size_t)(m0 >> 1) * 512);
        uint4* dst = (uint4*)(smem + HOFF);
#pragma unroll 8
        for (int i = tid; i < 8192; i += 256) dst[i] = src[i];
    }

    // A-builder identity: row r = tid>>1, half hsel = tid&1 (16 k-cols each)
    const int br = tid >> 1;
    const int hsel = tid & 1;
    const char* hrow0 = smem + HOFF + (br >> 1) * 2048 + hsel * 64;   // node 0
    const char* hrow1 = hrow0 + 1024;                                  // node 1
    char* aw_hi_base = smem + AOFF + br * PITCH + hsel * 32;
    char* aw_lo_base = aw_hi_base + 10240;
    char* bw_base    = smem + BOFF + (tid >> 2) * PITCH + (tid & 3) * 16;
    const int bn_glb = (n0g + (tid >> 2)) * 128;                       // uint4 row base
    const int bn_glb2 = (n0g + 64 + (tid >> 2)) * 128;
    float c0 = 0.f, c1 = 0.f;

    __syncthreads();    // h cache ready

    // ---- build chunk 0 into buf 0 ----
    {
        // B chunk 0
        uint4 v;
        v = g_Whi4[bn_glb + (tid & 3)];               *(uint4*)(bw_base) = v;
        v = g_Whi4[bn_glb2 + (tid & 3)];              *(uint4*)(bw_base + 64 * PITCH) = v;
        v = g_Wlo4[bn_glb + (tid & 3)];               *(uint4*)(bw_base + 10240) = v;
        v = g_Wlo4[bn_glb2 + (tid & 3)];              *(uint4*)(bw_base + 10240 + 64 * PITCH) = v;
        // A chunk 0 (head 0, fo = 0)
        float2 cc = ((const float2*)g_coef)[(size_t)(m0 + br) * 4 + 0];
        c0 = cc.x; c1 = cc.y;
        const float4* p0 = (const float4*)(hrow0);
        const float4* p1 = (const float4*)(hrow1);
        uint32_t hp[8], lp[8];
#pragma unroll
        for (int q = 0; q < 4; ++q) {
            float4 v0 = p0[q], v1 = p1[q];
            float x0 = c0 * v0.x + c1 * v1.x, x1 = c0 * v0.y + c1 * v1.y;
            float x2 = c0 * v0.z + c1 * v1.z, x3 = c0 * v0.w + c1 * v1.w;
            __nv_bfloat162 h01 = __floats2bfloat162_rn(x0, x1);
            __nv_bfloat162 h23 = __floats2bfloat162_rn(x2, x3);
            __nv_bfloat162 l01 = __floats2bfloat162_rn(x0 - __bfloat162float(h01.x), x1 - __bfloat162float(h01.y));
            __nv_bfloat162 l23 = __floats2bfloat162_rn(x2 - __bfloat162float(h23.x), x3 - __bfloat162float(h23.y));
            hp[q * 2] = *(uint32_t*)&h01; hp[q * 2 + 1] = *(uint32_t*)&h23;
            lp[q * 2] = *(uint32_t*)&l01; lp[q * 2 + 1] = *(uint32_t*)&l23;
        }
        ((uint4*)aw_hi_base)[0] = *(uint4*)&hp[0]; ((uint4*)(aw_hi_base + 16))[0] = *(uint4*)&hp[4];
        ((uint4*)aw_lo_base)[0] = *(uint4*)&lp[0]; ((uint4*)(aw_lo_base + 16))[0] = *(uint4*)&lp[4];
    }
    __syncthreads();    // buf 0 ready

    // ---- mma addressing (per warp) ----
    const int mband = (wid & 3) * 32;
    const int nband = (wid >> 2) * 64;
    const uint32_t arow = (uint32_t)(mband + (lane & 7) + ((lane >> 3) & 1) * 8);
    const uint32_t akof = (uint32_t)((lane >> 4) * 16);      // bytes
    const uint32_t aoff_l = arow * PITCH + akof;
    const uint32_t brow = (uint32_t)(nband + (lane & 7));
    const uint32_t bkof = (uint32_t)(((lane >> 3) & 1) * 16);
    const uint32_t boff_l = brow * PITCH + bkof;

    float acc[2][8][4];
#pragma unroll
    for (int mt = 0; mt < 2; ++mt)
#pragma unroll
        for (int nt = 0; nt < 8; ++nt)
#pragma unroll
            for (int e = 0; e < 4; ++e) acc[mt][nt][e] = 0.f;

    for (int c = 0; c < NKITER; ++c) {
        const int s = c & 1;
        const bool pf = (c < NKITER - 1);

        // prefetch next B chunk into registers (overlaps mma)
        uint4 pbh0, pbh1, pbl0, pbl1;
        if (pf) {
            int k4 = (c + 1) * 4 + (tid & 3);
            pbh0 = g_Whi4[bn_glb + k4];  pbh1 = g_Whi4[bn_glb2 + k4];
            pbl0 = g_Wlo4[bn_glb + k4];  pbl1 = g_Wlo4[bn_glb2 + k4];
        }

        // consume buffer s
        const uint32_t ahb = sb + AOFF + s * ABUFS + aoff_l;
        const uint32_t alb = ahb + 10240;
        const uint32_t bhb = sb + BOFF + s * BBUFS + boff_l;
        const uint32_t blb = bhb + 10240;
#pragma unroll
        for (int ks = 0; ks < 2; ++ks) {
            uint32_t ah[2][4], al[2][4];
            ldsm_x4(ah[0], ahb + ks * 32);
            ldsm_x4(ah[1], ahb + 16 * PITCH + ks * 32);
            ldsm_x4(al[0], alb + ks * 32);
            ldsm_x4(al[1], alb + 16 * PITCH + ks * 32);
#pragma unroll
            for (int nt = 0; nt < 8; ++nt) {
                uint32_t bh[2], bl[2];
                ldsm_x2(bh, bhb + nt * 8 * PITCH + ks * 32);
                ldsm_x2(bl, blb + nt * 8 * PITCH + ks * 32);
#pragma unroll
                for (int mt = 0; mt < 2; ++mt) {
                    mma_bf16(acc[mt][nt], ah[mt], bh);
                    mma_bf16(acc[mt][nt], ah[mt], bl);
                    mma_bf16(acc[mt][nt], al[mt], bh);
                }
            }
        }

        if (pf) {
            const int cn = c + 1;
            char* bw = bw_base + (cn & 1) * BBUFS;
            *(uint4*)(bw) = pbh0;
            *(uint4*)(bw + 64 * PITCH) = pbh1;
            *(uint4*)(bw + 10240) = pbl0;
            *(uint4*)(bw + 10240 + 64 * PITCH) = pbl1;

            if ((cn & 7) == 0) {
                float2 cc = ((const float2*)g_coef)[(size_t)(m0 + br) * 4 + (cn >> 3)];
                c0 = cc.x; c1 = cc.y;
            }
            const int fob = (cn & 7) * 128;              // byte offset of f window
            const float4* p0 = (const float4*)(hrow0 + fob);
            const float4* p1 = (const float4*)(hrow1 + fob);
            uint32_t hp[8], lp[8];
#pragma unroll
            for (int q = 0; q < 4; ++q) {
                float4 v0 = p0[q], v1 = p1[q];
                float x0 = c0 * v0.x + c1 * v1.x, x1 = c0 * v0.y + c1 * v1.y;
                float x2 = c0 * v0.z + c1 * v1.z, x3 = c0 * v0.w + c1 * v1.w;
                __nv_bfloat162 h01 = __floats2bfloat162_rn(x0, x1);
                __nv_bfloat162 h23 = __floats2bfloat162_rn(x2, x3);
                __nv_bfloat162 l01 = __floats2bfloat162_rn(x0 - __bfloat162float(h01.x), x1 - __bfloat162float(h01.y));
                __nv_bfloat162 l23 = __floats2bfloat162_rn(x2 - __bfloat162float(h23.x), x3 - __bfloat162float(h23.y));
                hp[q * 2] = *(uint32_t*)&h01; hp[q * 2 + 1] = *(uint32_t*)&h23;
                lp[q * 2] = *(uint32_t*)&l01; lp[q * 2 + 1] = *(uint32_t*)&l23;
            }
            char* awh = aw_hi_base + (cn & 1) * ABUFS;
            char* awl = aw_lo_base + (cn & 1) * ABUFS;
            ((uint4*)awh)[0] = *(uint4*)&hp[0]; ((uint4*)(awh + 16))[0] = *(uint4*)&hp[4];
            ((uint4*)awl)[0] = *(uint4*)&lp[0]; ((uint4*)(awl + 16))[0] = *(uint4*)&lp[4];
        }
        __syncthreads();
    }

    // ---- epilogue ----
    const int grow = m0 + mband + (lane >> 2);
    const int gcol = n0g + nband + (lane & 3) * 2;
#pragma unroll
    for (int mt = 0; mt < 2; ++mt) {
#pragma unroll
        for (int nt = 0; nt < 8; ++nt) {
            float* p = out + (size_t)(grow + mt * 16) * 256 + gcol + nt * 8;
            *(float2*)p = make_float2(acc[mt][nt][0], acc[mt][nt][1]);
            *(float2*)(p + 8 * 256) = make_float2(acc[mt][nt][2], acc[mt][nt][3]);
        }
    }
}

// ---------------------------------------------------------------------------
// Launch
// ---------------------------------------------------------------------------
extern "C" void kernel_launch(void* const* d_in, const int* in_sizes, int n_in,
                              void* d_out, int out_size) {
    const float* h   = (const float*)d_in[0];
    const int*   adj = (const int*)  d_in[1];
    const float* W   = (const float*)d_in[2];
    const float* a   = (const float*)d_in[3];
    float* out = (float*)d_out;

    cudaFuncSetAttribute(gat_main, cudaFuncAttributeMaxDynamicSharedMemorySize, SMEM_TOTAL);

    gat_prep<<<256, 256>>>(W, a);
    gat_prepB<<<1024, 256>>>(W);
    gat_attn<<<BATCH / 8, 256>>>(h, adj);
    gat_main<<<dim3(2, 1024), 256, SMEM_TOTAL>>>(h, out);
}

// round 6
// speedup vs baseline: 2.1966x; 1.0594x over previous
#include <cuda_runtime.h>
#include <cuda_bf16.h>
#include <math.h>
#include <stdint.h>

// Problem constants
#define BATCH   65536
#define NNODES  2
#define FIN     256
#define KDIM    1024
#define MROWS   131072
#define SLOPE   0.2f

// GEMM tiling
#define BM 128
#define BN 128
#define BK 32
#define NKITER 32               // 1024 / 32

// SMEM layout (bytes)
#define GPITCH 2064             // per-graph h pitch: 2048 data + 16 pad
#define HOFF   0                // h cache: 64 * GPITCH = 132096
#define COEF   132096           // 128 rows * 8 f32 = 4096
#define AOFF   136192           // A bufs: 2 * 20480
#define ABUFS  20480
#define BOFF   177152           // B bufs: 2 * 20480
#define BBUFS  20480
#define SMEM_TOTAL 218112
#define PITCH  80

#define NTHREADS 384            // warps 0-7 consumers, warps 8-11 producers

// Scratch
__device__ float g_wst[FIN * 8];
__device__ uint4 g_Whi4[32 * 1024];   // [kchunk][n 0..255][4 uint4]
__device__ uint4 g_Wlo4[32 * 1024];

__device__ __forceinline__ uint32_t smem_u32(const void* p) {
    uint32_t a;
    asm("{ .reg .u64 t; cvta.to.shared.u64 t, %1; cvt.u32.u64 %0, t; }" : "=r"(a) : "l"(p));
    return a;
}
__device__ __forceinline__ void ldsm_x4(uint32_t* r, uint32_t addr) {
    asm volatile("ldmatrix.sync.aligned.m8n8.x4.shared.b16 {%0,%1,%2,%3}, [%4];"
        : "=r"(r[0]), "=r"(r[1]), "=r"(r[2]), "=r"(r[3]) : "r"(addr));
}
__device__ __forceinline__ void mma_bf16(float* d, const uint32_t* a, const uint32_t* b) {
    asm volatile("mma.sync.aligned.m16n8k16.row.col.f32.bf16.bf16.f32 "
        "{%0,%1,%2,%3}, {%4,%5,%6,%7}, {%8,%9}, {%0,%1,%2,%3};"
        : "+f"(d[0]), "+f"(d[1]), "+f"(d[2]), "+f"(d[3])
        : "r"(a[0]), "r"(a[1]), "r"(a[2]), "r"(a[3]), "r"(b[0]), "r"(b[1]));
}

// ---------------------------------------------------------------------------
// Kernel 1: wst dot products. One warp per output, 2048 outputs.
// ---------------------------------------------------------------------------
__global__ void gat_prep(const float* __restrict__ W, const float* __restrict__ a) {
    int wid = threadIdx.x >> 5, lane = threadIdx.x & 31;
    int t = blockIdx.x * 8 + wid;
    int f = t >> 3, c = t & 7, hd = c & 3, tg = c >> 2;
    const float4* wrow = (const float4*)(W + f * KDIM + hd * 256);
    const float4* av   = (const float4*)(a + hd * 512 + tg * 256);
    float s = 0.f;
#pragma unroll
    for (int q = 0; q < 2; ++q) {
        int i = lane + q * 32;
        float4 w4 = wrow[i], a4 = av[i];
        s += w4.x * a4.x + w4.y * a4.y + w4.z * a4.z + w4.w * a4.w;
    }
#pragma unroll
    for (int off = 16; off > 0; off >>= 1) s += __shfl_xor_sync(0xFFFFFFFFu, s, off);
    if (lane == 0) g_wst[t] = s;
}

// ---------------------------------------------------------------------------
// Kernel 1b: split Wstack^T into bf16 hi/lo, chunk-major layout.
// ---------------------------------------------------------------------------
__global__ void gat_prepB(const float* __restrict__ W) {
    int idx = blockIdx.x * 256 + threadIdx.x;        // n*1024 + k
    int n = idx >> 10, k = idx & 1023;
    int f = k & 255, hd = k >> 8;
    float w = W[f * KDIM + hd * 256 + n];
    __nv_bfloat16 hi = __float2bfloat16(w);
    __nv_bfloat16 lo = __float2bfloat16(w - __bfloat162float(hi));
    int di = (k >> 5) * 8192 + n * 32 + (k & 31);
    ((__nv_bfloat16*)g_Whi4)[di] = hi;
    ((__nv_bfloat16*)g_Wlo4)[di] = lo;
}

// ---------------------------------------------------------------------------
// Kernel 2: warp-specialized GEMM with fused attention prologue.
// ---------------------------------------------------------------------------
__device__ __forceinline__ float lrelu(float x) { return x > 0.f ? x : SLOPE * x; }

__device__ __forceinline__ void produce_chunk(
    char* smem, int c, int r, const char* hrow0, const char* hrow1,
    const float2* coefp, const int bbase)
{
    const int buf = c & 1;
    uint4 bh[4], bl[4];
    const uint4* ph = g_Whi4 + c * 1024 + bbase;
    const uint4* pl = g_Wlo4 + c * 1024 + bbase;
#pragma unroll
    for (int j = 0; j < 4; ++j) { bh[j] = ph[j]; bl[j] = pl[j]; }

    const int hd = c >> 3;
    const int fob = (c & 7) * 128;
    float2 cc = coefp[hd];
    const float4* q0 = (const float4*)(hrow0 + fob);
    const float4* q1 = (const float4*)(hrow1 + fob);
    uint32_t hp[16], lp[16];
#pragma unroll
    for (int q = 0; q < 8; ++q) {
        float4 v0 = q0[q], v1 = q1[q];
        float x0 = cc.x * v0.x + cc.y * v1.x, x1 = cc.x * v0.y + cc.y * v1.y;
        float x2 = cc.x * v0.z + cc.y * v1.z, x3 = cc.x * v0.w + cc.y * v1.w;
        __nv_bfloat162 h01 = __floats2bfloat162_rn(x0, x1);
        __nv_bfloat162 h23 = __floats2bfloat162_rn(x2, x3);
        __nv_bfloat162 l01 = __floats2bfloat162_rn(x0 - __bfloat162float(h01.x),
                                                   x1 - __bfloat162float(h01.y));
        __nv_bfloat162 l23 = __floats2bfloat162_rn(x2 - __bfloat162float(h23.x),
                                                   x3 - __bfloat162float(h23.y));
        hp[q * 2] = *(uint32_t*)&h01; hp[q * 2 + 1] = *(uint32_t*)&h23;
        lp[q * 2] = *(uint32_t*)&l01; lp[q * 2 + 1] = *(uint32_t*)&l23;
    }
    char* awh = smem + AOFF + buf * ABUFS + r * PITCH;
    char* awl = awh + 10240;
    char* bw  = smem + BOFF + buf * BBUFS + r * PITCH;
#pragma unroll
    for (int j = 0; j < 4; ++j) {
        *(uint4*)(awh + j * 16) = *(uint4*)&hp[j * 4];
        *(uint4*)(awl + j * 16) = *(uint4*)&lp[j * 4];
        *(uint4*)(bw + j * 16) = bh[j];
        *(uint4*)(bw + 10240 + j * 16) = bl[j];
    }
}

__global__ void __launch_bounds__(NTHREADS, 1)
gat_main(const float* __restrict__ h, const int* __restrict__ adj,
         float* __restrict__ out) {
    extern __shared__ char smem[];
    const uint32_t sb = smem_u32(smem);
    const int tid = threadIdx.x;
    const int wid = tid >> 5;
    const int lane = tid & 31;
    const int m0 = blockIdx.y * BM;
    const int n0g = blockIdx.x * BN;

    // ---- prologue 1: copy h tile ----
    {
        const uint4* src = (const uint4*)(h + (size_t)(m0 >> 1) * 512);
        for (int i = tid; i < 8192; i += NTHREADS) {
            int g = i >> 7, j = i & 127;
            *(uint4*)(smem + HOFF + g * GPITCH + j * 16) = src[i];
        }
    }
    __syncthreads();

    // ---- prologue 2: fused attention (warp per graph) ----
    for (int g = wid; g < 64; g += 12) {
        const float* hb = (const float*)(smem + HOFF + g * GPITCH);
        float p[16];
#pragma unroll
        for (int c = 0; c < 16; ++c) p[c] = 0.f;
#pragma unroll
        for (int q = 0; q < 8; ++q) {
            int f = lane + q * 32;
            float h0 = hb[f];
            float h1 = hb[256 + f];
            const float4* wp = (const float4*)(g_wst + f * 8);
            float4 w0 = wp[0];
            float4 w1 = wp[1];
            p[0] += h0 * w0.x; p[1] += h0 * w0.y; p[2] += h0 * w0.z; p[3] += h0 * w0.w;
            p[4] += h0 * w1.x; p[5] += h0 * w1.y; p[6] += h0 * w1.z; p[7] += h0 * w1.w;
            p[8]  += h1 * w0.x; p[9]  += h1 * w0.y; p[10] += h1 * w0.z; p[11] += h1 * w0.w;
            p[12] += h1 * w1.x; p[13] += h1 * w1.y; p[14] += h1 * w1.z; p[15] += h1 * w1.w;
        }
#pragma unroll
        for (int off = 16; off > 0; off >>= 1) {
#pragma unroll
            for (int c = 0; c < 16; ++c) p[c] += __shfl_xor_sync(0xFFFFFFFFu, p[c], off);
        }
        if (lane == 0) {
            int b = (m0 >> 1) + g;
            int a00 = adj[b * 4 + 0], a01 = adj[b * 4 + 1];
            int a10 = adj[b * 4 + 2], a11 = adj[b * 4 + 3];
            float cf[16];
#pragma unroll
            for (int i = 0; i < 2; ++i) {
                int mk0 = (i == 0) ? a00 : a10;
                int mk1 = (i == 0) ? a01 : a11;
#pragma unroll
                for (int hd = 0; hd < 4; ++hd) {
                    float si = p[i * 8 + hd];
                    float e0 = lrelu(si + p[4 + hd]);
                    float e1 = lrelu(si + p[12 + hd]);
                    float mx = -INFINITY;
                    if (mk0) mx = e0;
                    if (mk1) mx = fmaxf(mx, e1);
                    float x0 = mk0 ? expf(e0 - mx) : 0.f;
                    float x1 = mk1 ? expf(e1 - mx) : 0.f;
                    float inv = 0.25f / (x0 + x1);
                    cf[i * 8 + hd * 2 + 0] = x0 * inv;
                    cf[i * 8 + hd * 2 + 1] = x1 * inv;
                }
            }
            float4* dst = (float4*)(smem + COEF + g * 64);
#pragma unroll
            for (int q = 0; q < 4; ++q) dst[q] = *(float4*)&cf[q * 4];
        }
    }
    __syncthreads();

    if (wid >= 8) {
        // ---------------- PRODUCER ----------------
        const int r = tid - 256;
        const char* hrow0 = smem + HOFF + (r >> 1) * GPITCH;
        const char* hrow1 = hrow0 + 1024;
        const float2* coefp = (const float2*)(smem + COEF + r * 32);
        const int bbase = n0g * 4 + r * 4;

        produce_chunk(smem, 0, r, hrow0, hrow1, coefp, bbase);
        __syncthreads();                       // chunk 0 visible
        for (int c = 0; c < NKITER; ++c) {
            if (c + 1 < NKITER)
                produce_chunk(smem, c + 1, r, hrow0, hrow1, coefp, bbase);
            __syncthreads();                   // chunk c+1 visible / buf c released
        }
    } else {
        // ---------------- CONSUMER ----------------
        const int mband = (wid & 3) * 32;
        const int nband = (wid >> 2) * 64;
        const uint32_t aoff_l = (uint32_t)((mband + (lane & 7) + ((lane >> 3) & 1) * 8) * PITCH
                                           + (lane >> 4) * 16);
        const uint32_t boff_l = (uint32_t)(((lane >> 4) ? 10240 : 0)
                                           + (nband + (lane & 7)) * PITCH
                                           + ((lane >> 3) & 1) * 16);
        float acc[2][8][4];
#pragma unroll
        for (int mt = 0; mt < 2; ++mt)
#pragma unroll
            for (int nt = 0; nt < 8; ++nt)
#pragma unroll
                for (int e = 0; e < 4; ++e) acc[mt][nt][e] = 0.f;

        __syncthreads();                       // chunk 0 ready
        for (int c = 0; c < NKITER; ++c) {
            const int s = c & 1;
            const uint32_t ahb = sb + AOFF + s * ABUFS + aoff_l;
            const uint32_t alb = ahb + 10240;
            const uint32_t bbb = sb + BOFF + s * BBUFS + boff_l;
#pragma unroll
            for (int ks = 0; ks < 2; ++ks) {
                uint32_t ah[2][4], al[2][4];
                ldsm_x4(ah[0], ahb + ks * 32);
                ldsm_x4(ah[1], ahb + 16 * PITCH + ks * 32);
                ldsm_x4(al[0], alb + ks * 32);
                ldsm_x4(al[1], alb + 16 * PITCH + ks * 32);
#pragma unroll
                for (int nt = 0; nt < 8; ++nt) {
                    uint32_t bb[4];
                    ldsm_x4(bb, bbb + nt * 8 * PITCH + ks * 32);
#pragma unroll
                    for (int mt = 0; mt < 2; ++mt) {
                        mma_bf16(acc[mt][nt], ah[mt], bb);
                        mma_bf16(acc[mt][nt], ah[mt], bb + 2);
                        mma_bf16(acc[mt][nt], al[mt], bb);
                    }
                }
            }
            __syncthreads();                   // next chunk ready / buf released
        }

        const int grow = m0 + mband + (lane >> 2);
        const int gcol = n0g + nband + (lane & 3) * 2;
#pragma unroll
        for (int mt = 0; mt < 2; ++mt) {
#pragma unroll
            for (int nt = 0; nt < 8; ++nt) {
                float* p = out + (size_t)(grow + mt * 16) * 256 + gcol + nt * 8;
                *(float2*)p = make_float2(acc[mt][nt][0], acc[mt][nt][1]);
                *(float2*)(p + 8 * 256) = make_float2(acc[mt][nt][2], acc[mt][nt][3]);
            }
        }
    }
}

// ---------------------------------------------------------------------------
// Launch
// ---------------------------------------------------------------------------
extern "C" void kernel_launch(void* const* d_in, const int* in_sizes, int n_in,
                              void* d_out, int out_size) {
    const float* h   = (const float*)d_in[0];
    const int*   adj = (const int*)  d_in[1];
    const float* W   = (const float*)d_in[2];
    const float* a   = (const float*)d_in[3];
    float* out = (float*)d_out;

    cudaFuncSetAttribute(gat_main, cudaFuncAttributeMaxDynamicSharedMemorySize, SMEM_TOTAL);

    gat_prep<<<256, 256>>>(W, a);
    gat_prepB<<<1024, 256>>>(W);
    gat_main<<<dim3(2, 1024), NTHREADS, SMEM_TOTAL>>>(h, adj, out);
}

// round 8
// speedup vs baseline: 2.2027x; 1.0028x over previous
#include <cuda_runtime.h>
#include <cuda_bf16.h>
#include <math.h>
#include <stdint.h>

// Problem constants
#define BATCH   65536
#define NNODES  2
#define FIN     256
#define KDIM    1024
#define MROWS   131072
#define SLOPE   0.2f

// GEMM tiling
#define BM 128
#define BN 128
#define BK 32
#define NKITER 32               // 1024 / 32

// SMEM layout (bytes)
#define GPITCH 2064             // per-graph h pitch: 2048 data + 16 pad
#define HOFF   0                // h cache: 64 * GPITCH = 132096
#define COEF   132096           // 128 rows * 8 f32 = 4096
#define AOFF   136192           // A bufs: 2 * 20480
#define ABUFS  20480
#define BOFF   177152           // B bufs: 2 * 20480
#define BBUFS  20480
#define SMEM_TOTAL 218112
#define PITCH  80

#define NTHREADS 384            // warps 0-7 consumers, warps 8-11 producers

// Scratch
__device__ float g_wst[FIN * 8];
__device__ uint4 g_Whi4[32 * 1024];   // [kchunk][n 0..255][4 uint4]
__device__ uint4 g_Wlo4[32 * 1024];

__device__ __forceinline__ uint32_t smem_u32(const void* p) {
    uint32_t a;
    asm("{ .reg .u64 t; cvta.to.shared.u64 t, %1; cvt.u32.u64 %0, t; }" : "=r"(a) : "l"(p));
    return a;
}
__device__ __forceinline__ void ldsm_x4(uint32_t* r, uint32_t addr) {
    asm volatile("ldmatrix.sync.aligned.m8n8.x4.shared.b16 {%0,%1,%2,%3}, [%4];"
        : "=r"(r[0]), "=r"(r[1]), "=r"(r[2]), "=r"(r[3]) : "r"(addr));
}
__device__ __forceinline__ void mma_bf16(float* d, const uint32_t* a, const uint32_t* b) {
    asm volatile("mma.sync.aligned.m16n8k16.row.col.f32.bf16.bf16.f32 "
        "{%0,%1,%2,%3}, {%4,%5,%6,%7}, {%8,%9}, {%0,%1,%2,%3};"
        : "+f"(d[0]), "+f"(d[1]), "+f"(d[2]), "+f"(d[3])
        : "r"(a[0]), "r"(a[1]), "r"(a[2]), "r"(a[3]), "r"(b[0]), "r"(b[1]));
}

// ---------------------------------------------------------------------------
// Kernel 1: wst dot products. One warp per output, 2048 outputs.
// ---------------------------------------------------------------------------
__global__ void gat_prep(const float* __restrict__ W, const float* __restrict__ a) {
    int wid = threadIdx.x >> 5, lane = threadIdx.x & 31;
    int t = blockIdx.x * 8 + wid;
    int f = t >> 3, c = t & 7, hd = c & 3, tg = c >> 2;
    const float4* wrow = (const float4*)(W + f * KDIM + hd * 256);
    const float4* av   = (const float4*)(a + hd * 512 + tg * 256);
    float s = 0.f;
#pragma unroll
    for (int q = 0; q < 2; ++q) {
        int i = lane + q * 32;
        float4 w4 = wrow[i], a4 = av[i];
        s += w4.x * a4.x + w4.y * a4.y + w4.z * a4.z + w4.w * a4.w;
    }
#pragma unroll
    for (int off = 16; off > 0; off >>= 1) s += __shfl_xor_sync(0xFFFFFFFFu, s, off);
    if (lane == 0) g_wst[t] = s;
}

// ---------------------------------------------------------------------------
// Kernel 1b: split Wstack^T into bf16 hi/lo, chunk-major layout.
// ---------------------------------------------------------------------------
__global__ void gat_prepB(const float* __restrict__ W) {
    int idx = blockIdx.x * 256 + threadIdx.x;        // n*1024 + k
    int n = idx >> 10, k = idx & 1023;
    int f = k & 255, hd = k >> 8;
    float w = W[f * KDIM + hd * 256 + n];
    __nv_bfloat16 hi = __float2bfloat16(w);
    __nv_bfloat16 lo = __float2bfloat16(w - __bfloat162float(hi));
    int di = (k >> 5) * 8192 + n * 32 + (k & 31);
    ((__nv_bfloat16*)g_Whi4)[di] = hi;
    ((__nv_bfloat16*)g_Wlo4)[di] = lo;
}

// ---------------------------------------------------------------------------
// Kernel 2: warp-specialized GEMM with fused attention prologue.
// ---------------------------------------------------------------------------
__device__ __forceinline__ float lrelu(float x) { return x > 0.f ? x : SLOPE * x; }

__device__ __forceinline__ void produce_chunk(
    char* smem, int c, int r, const char* hrow0, const char* hrow1,
    const float2* coefp, const int bbase)
{
    const int buf = c & 1;
    uint4 bh[4], bl[4];
    const uint4* ph = g_Whi4 + c * 1024 + bbase;
    const uint4* pl = g_Wlo4 + c * 1024 + bbase;
#pragma unroll
    for (int j = 0; j < 4; ++j) { bh[j] = ph[j]; bl[j] = pl[j]; }

    const int hd = c >> 3;
    const int fob = (c & 7) * 128;
    float2 cc = coefp[hd];
    const float4* q0 = (const float4*)(hrow0 + fob);
    const float4* q1 = (const float4*)(hrow1 + fob);
    uint32_t hp[16], lp[16];
#pragma unroll
    for (int q = 0; q < 8; ++q) {
        float4 v0 = q0[q], v1 = q1[q];
        float x0 = cc.x * v0.x + cc.y * v1.x, x1 = cc.x * v0.y + cc.y * v1.y;
        float x2 = cc.x * v0.z + cc.y * v1.z, x3 = cc.x * v0.w + cc.y * v1.w;
        __nv_bfloat162 h01 = __floats2bfloat162_rn(x0, x1);
        __nv_bfloat162 h23 = __floats2bfloat162_rn(x2, x3);
        __nv_bfloat162 l01 = __floats2bfloat162_rn(x0 - __bfloat162float(h01.x),
                                                   x1 - __bfloat162float(h01.y));
        __nv_bfloat162 l23 = __floats2bfloat162_rn(x2 - __bfloat162float(h23.x),
                                                   x3 - __bfloat162float(h23.y));
        hp[q * 2] = *(uint32_t*)&h01; hp[q * 2 + 1] = *(uint32_t*)&h23;
        lp[q * 2] = *(uint32_t*)&l01; lp[q * 2 + 1] = *(uint32_t*)&l23;
    }
    char* awh = smem + AOFF + buf * ABUFS + r * PITCH;
    char* awl = awh + 10240;
    char* bw  = smem + BOFF + buf * BBUFS + r * PITCH;
#pragma unroll
    for (int j = 0; j < 4; ++j) {
        *(uint4*)(awh + j * 16) = *(uint4*)&hp[j * 4];
        *(uint4*)(awl + j * 16) = *(uint4*)&lp[j * 4];
        *(uint4*)(bw + j * 16) = bh[j];
        *(uint4*)(bw + 10240 + j * 16) = bl[j];
    }
}

__global__ void __launch_bounds__(NTHREADS, 1)
gat_main(const float* __restrict__ h, const int* __restrict__ adj,
         float* __restrict__ out) {
    extern __shared__ char smem[];
    const uint32_t sb = smem_u32(smem);
    const int tid = threadIdx.x;
    const int wid = tid >> 5;
    const int lane = tid & 31;
    const int m0 = blockIdx.y * BM;
    const int n0g = blockIdx.x * BN;

    // ---- prologue 1: copy h tile ----
    {
        const uint4* src = (const uint4*)(h + (size_t)(m0 >> 1) * 512);
        for (int i = tid; i < 8192; i += NTHREADS) {
            int g = i >> 7, j = i & 127;
            *(uint4*)(smem + HOFF + g * GPITCH + j * 16) = src[i];
        }
    }
    __syncthreads();

    // ---- prologue 2: fused attention (warp per graph) ----
    for (int g = wid; g < 64; g += 12) {
        const float* hb = (const float*)(smem + HOFF + g * GPITCH);
        float p[16];
#pragma unroll
        for (int c = 0; c < 16; ++c) p[c] = 0.f;
#pragma unroll
        for (int q = 0; q < 8; ++q) {
            int f = lane + q * 32;
            float h0 = hb[f];
            float h1 = hb[256 + f];
            const float4* wp = (const float4*)(g_wst + f * 8);
            float4 w0 = wp[0];
            float4 w1 = wp[1];
            p[0] += h0 * w0.x; p[1] += h0 * w0.y; p[2] += h0 * w0.z; p[3] += h0 * w0.w;
            p[4] += h0 * w1.x; p[5] += h0 * w1.y; p[6] += h0 * w1.z; p[7] += h0 * w1.w;
            p[8]  += h1 * w0.x; p[9]  += h1 * w0.y; p[10] += h1 * w0.z; p[11] += h1 * w0.w;
            p[12] += h1 * w1.x; p[13] += h1 * w1.y; p[14] += h1 * w1.z; p[15] += h1 * w1.w;
        }
#pragma unroll
        for (int off = 16; off > 0; off >>= 1) {
#pragma unroll
            for (int c = 0; c < 16; ++c) p[c] += __shfl_xor_sync(0xFFFFFFFFu, p[c], off);
        }
        if (lane == 0) {
            int b = (m0 >> 1) + g;
            int a00 = adj[b * 4 + 0], a01 = adj[b * 4 + 1];
            int a10 = adj[b * 4 + 2], a11 = adj[b * 4 + 3];
            float cf[16];
#pragma unroll
            for (int i = 0; i < 2; ++i) {
                int mk0 = (i == 0) ? a00 : a10;
                int mk1 = (i == 0) ? a01 : a11;
#pragma unroll
                for (int hd = 0; hd < 4; ++hd) {
                    float si = p[i * 8 + hd];
                    float e0 = lrelu(si + p[4 + hd]);
                    float e1 = lrelu(si + p[12 + hd]);
                    float mx = -INFINITY;
                    if (mk0) mx = e0;
                    if (mk1) mx = fmaxf(mx, e1);
                    float x0 = mk0 ? expf(e0 - mx) : 0.f;
                    float x1 = mk1 ? expf(e1 - mx) : 0.f;
                    float inv = 0.25f / (x0 + x1);
                    cf[i * 8 + hd * 2 + 0] = x0 * inv;
                    cf[i * 8 + hd * 2 + 1] = x1 * inv;
                }
            }
            float4* dst = (float4*)(smem + COEF + g * 64);
#pragma unroll
            for (int q = 0; q < 4; ++q) dst[q] = *(float4*)&cf[q * 4];
        }
    }
    __syncthreads();

    if (wid >= 8) {
        // ---------------- PRODUCER ----------------
        const int r = tid - 256;
        const char* hrow0 = smem + HOFF + (r >> 1) * GPITCH;
        const char* hrow1 = hrow0 + 1024;
        const float2* coefp = (const float2*)(smem + COEF + r * 32);
        const int bbase = n0g * 4 + r * 4;

        produce_chunk(smem, 0, r, hrow0, hrow1, coefp, bbase);
        __syncthreads();                       // chunk 0 visible
        for (int c = 0; c < NKITER; ++c) {
            if (c + 1 < NKITER)
                produce_chunk(smem, c + 1, r, hrow0, hrow1, coefp, bbase);
            __syncthreads();                   // chunk c+1 visible / buf c released
        }
    } else {
        // ---------------- CONSUMER ----------------
        const int mband = (wid & 3) * 32;
        const int nband = (wid >> 2) * 64;
        const uint32_t aoff_l = (uint32_t)((mband + (lane & 7) + ((lane >> 3) & 1) * 8) * PITCH
                                           + (lane >> 4) * 16);
        const uint32_t boff_l = (uint32_t)(((lane >> 4) ? 10240 : 0)
                                           + (nband + (lane & 7)) * PITCH
                                           + ((lane >> 3) & 1) * 16);
        float acc[2][8][4];
#pragma unroll
        for (int mt = 0; mt < 2; ++mt)
#pragma unroll
            for (int nt = 0; nt < 8; ++nt)
#pragma unroll
                for (int e = 0; e < 4; ++e) acc[mt][nt][e] = 0.f;

        __syncthreads();                       // chunk 0 ready
        for (int c = 0; c < NKITER; ++c) {
            const int s = c & 1;
            const uint32_t ahb = sb + AOFF + s * ABUFS + aoff_l;
            const uint32_t alb = ahb + 10240;
            const uint32_t bbb = sb + BOFF + s * BBUFS + boff_l;
#pragma unroll
            for (int ks = 0; ks < 2; ++ks) {
                uint32_t ah[2][4], al[2][4], bb[8][4];
                ldsm_x4(ah[0], ahb + ks * 32);
                ldsm_x4(ah[1], ahb + 16 * PITCH + ks * 32);
                ldsm_x4(al[0], alb + ks * 32);
                ldsm_x4(al[1], alb + 16 * PITCH + ks * 32);
#pragma unroll
                for (int nt = 0; nt < 8; ++nt)
                    ldsm_x4(bb[nt], bbb + nt * 8 * PITCH + ks * 32);

                // term-major issue order: dependent MMAs on the same accumulator
                // are 16 independent MMAs apart (covers HMMA RAW latency).
#pragma unroll
                for (int mt = 0; mt < 2; ++mt)
#pragma unroll
                    for (int nt = 0; nt < 8; ++nt)
                        mma_bf16(acc[mt][nt], ah[mt], bb[nt]);        // Ahi*Bhi
#pragma unroll
                for (int mt = 0; mt < 2; ++mt)
#pragma unroll
                    for (int nt = 0; nt < 8; ++nt)
                        mma_bf16(acc[mt][nt], ah[mt], bb[nt] + 2);    // Ahi*Blo
#pragma unroll
                for (int mt = 0; mt < 2; ++mt)
#pragma unroll
                    for (int nt = 0; nt < 8; ++nt)
                        mma_bf16(acc[mt][nt], al[mt], bb[nt]);        // Alo*Bhi
            }
            __syncthreads();                   // next chunk ready / buf released
        }

        const int grow = m0 + mband + (lane >> 2);
        const int gcol = n0g + nband + (lane & 3) * 2;
#pragma unroll
        for (int mt = 0; mt < 2; ++mt) {
#pragma unroll
            for (int nt = 0; nt < 8; ++nt) {
                float* p = out + (size_t)(grow + mt * 16) * 256 + gcol + nt * 8;
                *(float2*)p = make_float2(acc[mt][nt][0], acc[mt][nt][1]);
                *(float2*)(p + 8 * 256) = make_float2(acc[mt][nt][2], acc[mt][nt][3]);
            }
        }
    }
}

// ---------------------------------------------------------------------------
// Launch
// ---------------------------------------------------------------------------
extern "C" void kernel_launch(void* const* d_in, const int* in_sizes, int n_in,
                              void* d_out, int out_size) {
    const float* h   = (const float*)d_in[0];
    const int*   adj = (const int*)  d_in[1];
    const float* W   = (const float*)d_in[2];
    const float* a   = (const float*)d_in[3];
    float* out = (float*)d_out;

    cudaFuncSetAttribute(gat_main, cudaFuncAttributeMaxDynamicSharedMemorySize, SMEM_TOTAL);

    gat_prep<<<256, 256>>>(W, a);
    gat_prepB<<<1024, 256>>>(W);
    gat_main<<<dim3(2, 1024), NTHREADS, SMEM_TOTAL>>>(h, adj, out);
}

// round 9
// speedup vs baseline: 2.2031x; 1.0002x over previous
#include <cuda_runtime.h>
#include <cuda_bf16.h>
#include <math.h>
#include <stdint.h>

// Problem constants
#define BATCH   65536
#define NNODES  2
#define FIN     256
#define KDIM    1024
#define MROWS   131072
#define SLOPE   0.2f

// GEMM tiling
#define BM 128
#define BN 128
#define BK 64
#define NKITER 16               // 1024 / 64

// SMEM layout (bytes)
#define COEF   0                // 128 rows * 8 f32 = 4096
#define AOFF   4096             // A bufs: 2 * 36864 (hi 18432 + lo 18432)
#define ABUF   36864
#define SPLITO 18432            // lo offset within a buf
#define BOFF   77824            // B bufs: 2 * 36864
#define BBUF   36864
#define SMEM_TOTAL 151552
#define PITCH  144              // 64 bf16 = 128B data + 16B pad (bank stride 4 mod 32)

#define NTHREADS 384            // warps 0-7 consumers, warps 8-11 producers

// Scratch: Wstack^T bf16 hi/lo, chunk-major [kc 0..15][n 0..255][64 bf16]
__device__ float g_wst[FIN * 8];
__device__ __nv_bfloat16 g_Whi[16 * 256 * 64];
__device__ __nv_bfloat16 g_Wlo[16 * 256 * 64];

__device__ __forceinline__ uint32_t smem_u32(const void* p) {
    uint32_t a;
    asm("{ .reg .u64 t; cvta.to.shared.u64 t, %1; cvt.u32.u64 %0, t; }" : "=r"(a) : "l"(p));
    return a;
}
__device__ __forceinline__ void ldsm_x4(uint32_t* r, uint32_t addr) {
    asm volatile("ldmatrix.sync.aligned.m8n8.x4.shared.b16 {%0,%1,%2,%3}, [%4];"
        : "=r"(r[0]), "=r"(r[1]), "=r"(r[2]), "=r"(r[3]) : "r"(addr));
}
__device__ __forceinline__ void mma_bf16(float* d, const uint32_t* a, const uint32_t* b) {
    asm volatile("mma.sync.aligned.m16n8k16.row.col.f32.bf16.bf16.f32 "
        "{%0,%1,%2,%3}, {%4,%5,%6,%7}, {%8,%9}, {%0,%1,%2,%3};"
        : "+f"(d[0]), "+f"(d[1]), "+f"(d[2]), "+f"(d[3])
        : "r"(a[0]), "r"(a[1]), "r"(a[2]), "r"(a[3]), "r"(b[0]), "r"(b[1]));
}
__device__ __forceinline__ void cp_async16(uint32_t daddr, const void* src) {
    asm volatile("cp.async.cg.shared.global [%0], [%1], 16;"
        :: "r"(daddr), "l"(src) : "memory");
}
__device__ __forceinline__ void cp_async_wait_all() {
    asm volatile("cp.async.wait_all;" ::: "memory");
}

// ---------------------------------------------------------------------------
// Kernel 1: wst dot products. One warp per output, 2048 outputs.
// ---------------------------------------------------------------------------
__global__ void gat_prep(const float* __restrict__ W, const float* __restrict__ a) {
    int wid = threadIdx.x >> 5, lane = threadIdx.x & 31;
    int t = blockIdx.x * 8 + wid;
    int f = t >> 3, c = t & 7, hd = c & 3, tg = c >> 2;
    const float4* wrow = (const float4*)(W + f * KDIM + hd * 256);
    const float4* av   = (const float4*)(a + hd * 512 + tg * 256);
    float s = 0.f;
#pragma unroll
    for (int q = 0; q < 2; ++q) {
        int i = lane + q * 32;
        float4 w4 = wrow[i], a4 = av[i];
        s += w4.x * a4.x + w4.y * a4.y + w4.z * a4.z + w4.w * a4.w;
    }
#pragma unroll
    for (int off = 16; off > 0; off >>= 1) s += __shfl_xor_sync(0xFFFFFFFFu, s, off);
    if (lane == 0) g_wst[t] = s;
}

// ---------------------------------------------------------------------------
// Kernel 1b: split Wstack^T into bf16 hi/lo, 64-wide chunk-major layout.
// Wt[n][k] = W[k&255][(k>>8)*256 + n]; dest = (k>>6)*16384 + n*64 + (k&63)
// ---------------------------------------------------------------------------
__global__ void gat_prepB(const float* __restrict__ W) {
    int idx = blockIdx.x * 256 + threadIdx.x;        // n*1024 + k
    int n = idx >> 10, k = idx & 1023;
    float w = W[(k & 255) * KDIM + (k >> 8) * 256 + n];
    __nv_bfloat16 hi = __float2bfloat16(w);
    __nv_bfloat16 lo = __float2bfloat16(w - __bfloat162float(hi));
    int di = (k >> 6) * 16384 + n * 64 + (k & 63);
    g_Whi[di] = hi;
    g_Wlo[di] = lo;
}

// ---------------------------------------------------------------------------
// Kernel 2: warp-specialized GEMM (BK=64) with fused attention prologue.
// ---------------------------------------------------------------------------
__device__ __forceinline__ float lrelu(float x) { return x > 0.f ? x : SLOPE * x; }

__device__ __forceinline__ void produce_chunk(
    char* smem, uint32_t sb, int c, int r, int n0g,
    const float* hp0, const float* hp1, const float2* coefp)
{
    const int buf = c & 1;

    // ---- B: cp.async straight GMEM -> SMEM (no registers, no STS) ----
    {
        const uint32_t dbase = sb + BOFF + buf * BBUF;
        const char* srcHi = (const char*)g_Whi + c * 32768 + n0g * 128;
        const char* srcLo = (const char*)g_Wlo + c * 32768 + n0g * 128;
#pragma unroll
        for (int g2 = 0; g2 < 8; ++g2) {
            int unit = r + 128 * g2;                 // 0..1023
            int n = unit >> 3, j = unit & 7;
            cp_async16(dbase + n * PITCH + j * 16, srcHi + n * 128 + j * 16);
        }
#pragma unroll
        for (int g2 = 0; g2 < 8; ++g2) {
            int unit = r + 128 * g2;
            int n = unit >> 3, j = unit & 7;
            cp_async16(dbase + SPLITO + n * PITCH + j * 16, srcLo + n * 128 + j * 16);
        }
    }

    // ---- A: build 64 k-values for row r from h (GMEM/L2), split, STS ----
    const int hd = c >> 2;
    const int fo = (c & 3) * 64;
    float2 cc = coefp[hd];
    const float4* q0 = (const float4*)(hp0 + fo);
    const float4* q1 = (const float4*)(hp1 + fo);
    char* awh = smem + AOFF + buf * ABUF + r * PITCH;
    char* awl = awh + SPLITO;
#pragma unroll
    for (int s8 = 0; s8 < 8; ++s8) {                 // strips of 8 floats
        float4 a0 = q0[s8 * 2], a1 = q0[s8 * 2 + 1];
        float4 b0 = q1[s8 * 2], b1 = q1[s8 * 2 + 1];
        float x0 = cc.x * a0.x + cc.y * b0.x, x1 = cc.x * a0.y + cc.y * b0.y;
        float x2 = cc.x * a0.z + cc.y * b0.z, x3 = cc.x * a0.w + cc.y * b0.w;
        float x4 = cc.x * a1.x + cc.y * b1.x, x5 = cc.x * a1.y + cc.y * b1.y;
        float x6 = cc.x * a1.z + cc.y * b1.z, x7 = cc.x * a1.w + cc.y * b1.w;
        __nv_bfloat162 h01 = __floats2bfloat162_rn(x0, x1);
        __nv_bfloat162 h23 = __floats2bfloat162_rn(x2, x3);
        __nv_bfloat162 h45 = __floats2bfloat162_rn(x4, x5);
        __nv_bfloat162 h67 = __floats2bfloat162_rn(x6, x7);
        __nv_bfloat162 l01 = __floats2bfloat162_rn(x0 - __bfloat162float(h01.x),
                                                   x1 - __bfloat162float(h01.y));
        __nv_bfloat162 l23 = __floats2bfloat162_rn(x2 - __bfloat162float(h23.x),
                                                   x3 - __bfloat162float(h23.y));
        __nv_bfloat162 l45 = __floats2bfloat162_rn(x4 - __bfloat162float(h45.x),
                                                   x5 - __bfloat162float(h45.y));
        __nv_bfloat162 l67 = __floats2bfloat162_rn(x6 - __bfloat162float(h67.x),
                                                   x7 - __bfloat162float(h67.y));
        uint4 hv, lv;
        hv.x = *(uint32_t*)&h01; hv.y = *(uint32_t*)&h23;
        hv.z = *(uint32_t*)&h45; hv.w = *(uint32_t*)&h67;
        lv.x = *(uint32_t*)&l01; lv.y = *(uint32_t*)&l23;
        lv.z = *(uint32_t*)&l45; lv.w = *(uint32_t*)&l67;
        *(uint4*)(awh + s8 * 16) = hv;
        *(uint4*)(awl + s8 * 16) = lv;
    }
    cp_async_wait_all();                             // B granules landed
}

__global__ void __launch_bounds__(NTHREADS, 1)
gat_main(const float* __restrict__ h, const int* __restrict__ adj,
         float* __restrict__ out) {
    extern __shared__ char smem[];
    const uint32_t sb = smem_u32(smem);
    const int tid = threadIdx.x;
    const int wid = tid >> 5;
    const int lane = tid & 31;
    const int m0 = blockIdx.y * BM;
    const int n0g = blockIdx.x * BN;

    // ---- prologue: fused attention coefficients (warp per graph, h from GMEM) ----
    for (int g = wid; g < 64; g += 12) {
        const float* hb = h + (size_t)((m0 >> 1) + g) * 512;
        float p[16];
#pragma unroll
        for (int c = 0; c < 16; ++c) p[c] = 0.f;
#pragma unroll
        for (int q = 0; q < 8; ++q) {
            int f = lane + q * 32;
            float h0 = hb[f];
            float h1 = hb[256 + f];
            const float4* wp = (const float4*)(g_wst + f * 8);
            float4 w0 = wp[0];
            float4 w1 = wp[1];
            p[0] += h0 * w0.x; p[1] += h0 * w0.y; p[2] += h0 * w0.z; p[3] += h0 * w0.w;
            p[4] += h0 * w1.x; p[5] += h0 * w1.y; p[6] += h0 * w1.z; p[7] += h0 * w1.w;
            p[8]  += h1 * w0.x; p[9]  += h1 * w0.y; p[10] += h1 * w0.z; p[11] += h1 * w0.w;
            p[12] += h1 * w1.x; p[13] += h1 * w1.y; p[14] += h1 * w1.z; p[15] += h1 * w1.w;
        }
#pragma unroll
        for (int off = 16; off > 0; off >>= 1) {
#pragma unroll
            for (int c = 0; c < 16; ++c) p[c] += __shfl_xor_sync(0xFFFFFFFFu, p[c], off);
        }
        if (lane == 0) {
            int b = (m0 >> 1) + g;
            int a00 = adj[b * 4 + 0], a01 = adj[b * 4 + 1];
            int a10 = adj[b * 4 + 2], a11 = adj[b * 4 + 3];
            float cf[16];
#pragma unroll
            for (int i = 0; i < 2; ++i) {
                int mk0 = (i == 0) ? a00 : a10;
                int mk1 = (i == 0) ? a01 : a11;
#pragma unroll
                for (int hd = 0; hd < 4; ++hd) {
                    float si = p[i * 8 + hd];
                    float e0 = lrelu(si + p[4 + hd]);
                    float e1 = lrelu(si + p[12 + hd]);
                    float mx = -INFINITY;
                    if (mk0) mx = e0;
                    if (mk1) mx = fmaxf(mx, e1);
                    float x0 = mk0 ? expf(e0 - mx) : 0.f;
                    float x1 = mk1 ? expf(e1 - mx) : 0.f;
                    float inv = 0.25f / (x0 + x1);
                    cf[i * 8 + hd * 2 + 0] = x0 * inv;
                    cf[i * 8 + hd * 2 + 1] = x1 * inv;
                }
            }
            float4* dst = (float4*)(smem + COEF + g * 64);
#pragma unroll
            for (int q = 0; q < 4; ++q) dst[q] = *(float4*)&cf[q * 4];
        }
    }
    __syncthreads();

    if (wid >= 8) {
        // ---------------- PRODUCER (warps 8-11) ----------------
        const int r = tid - 256;                     // 0..127: A row / granule id
        const int row = m0 + r;
        const float* hp0 = h + (size_t)(row >> 1) * 512;
        const float* hp1 = hp0 + 256;
        const float2* coefp = (const float2*)(smem + COEF + r * 32);

        produce_chunk(smem, sb, 0, r, n0g, hp0, hp1, coefp);
        __syncthreads();                             // chunk 0 visible
        for (int c = 0; c < NKITER; ++c) {
            if (c + 1 < NKITER)
                produce_chunk(smem, sb, c + 1, r, n0g, hp0, hp1, coefp);
            __syncthreads();                         // chunk c+1 visible / buf c released
        }
    } else {
        // ---------------- CONSUMER (warps 0-7) ----------------
        const int mband = (wid & 3) * 32;
        const int nband = (wid >> 2) * 64;
        const uint32_t aoff_l = (uint32_t)((mband + (lane & 7) + ((lane >> 3) & 1) * 8) * PITCH
                                           + (lane >> 4) * 16);
        const uint32_t boff_l = (uint32_t)(((lane >> 4) ? SPLITO : 0)
                                           + (nband + (lane & 7)) * PITCH
                                           + ((lane >> 3) & 1) * 16);
        float acc[2][8][4];
#pragma unroll
        for (int mt = 0; mt < 2; ++mt)
#pragma unroll
            for (int nt = 0; nt < 8; ++nt)
#pragma unroll
                for (int e = 0; e < 4; ++e) acc[mt][nt][e] = 0.f;

        __syncthreads();                             // chunk 0 ready
        for (int c = 0; c < NKITER; ++c) {
            const int s = c & 1;
            const uint32_t ahb = sb + AOFF + s * ABUF + aoff_l;
            const uint32_t alb = ahb + SPLITO;
            const uint32_t bbb = sb + BOFF + s * BBUF + boff_l;
#pragma unroll
            for (int ks = 0; ks < 4; ++ks) {
                uint32_t ah[2][4], al[2][4], bb[8][4];
                ldsm_x4(ah[0], ahb + ks * 32);
                ldsm_x4(ah[1], ahb + 16 * PITCH + ks * 32);
                ldsm_x4(al[0], alb + ks * 32);
                ldsm_x4(al[1], alb + 16 * PITCH + ks * 32);
#pragma unroll
                for (int nt = 0; nt < 8; ++nt)
                    ldsm_x4(bb[nt], bbb + nt * 8 * PITCH + ks * 32);

                // term-major: dependent MMAs on one accumulator are 16 apart
#pragma unroll
                for (int mt = 0; mt < 2; ++mt)
#pragma unroll
                    for (int nt = 0; nt < 8; ++nt)
                        mma_bf16(acc[mt][nt], ah[mt], bb[nt]);        // Ahi*Bhi
#pragma unroll
                for (int mt = 0; mt < 2; ++mt)
#pragma unroll
                    for (int nt = 0; nt < 8; ++nt)
                        mma_bf16(acc[mt][nt], ah[mt], bb[nt] + 2);    // Ahi*Blo
#pragma unroll
                for (int mt = 0; mt < 2; ++mt)
#pragma unroll
                    for (int nt = 0; nt < 8; ++nt)
                        mma_bf16(acc[mt][nt], al[mt], bb[nt]);        // Alo*Bhi
            }
            __syncthreads();                         // next chunk ready / buf released
        }

        // ---- epilogue ----
        const int grow = m0 + mband + (lane >> 2);
        const int gcol = n0g + nband + (lane & 3) * 2;
#pragma unroll
        for (int mt = 0; mt < 2; ++mt) {
#pragma unroll
            for (int nt = 0; nt < 8; ++nt) {
                float* p = out + (size_t)(grow + mt * 16) * 256 + gcol + nt * 8;
                *(float2*)p = make_float2(acc[mt][nt][0], acc[mt][nt][1]);
                *(float2*)(p + 8 * 256) = make_float2(acc[mt][nt][2], acc[mt][nt][3]);
            }
        }
    }
}

// ---------------------------------------------------------------------------
// Launch
// ---------------------------------------------------------------------------
extern "C" void kernel_launch(void* const* d_in, const int* in_sizes, int n_in,
                              void* d_out, int out_size) {
    const float* h   = (const float*)d_in[0];
    const int*   adj = (const int*)  d_in[1];
    const float* W   = (const float*)d_in[2];
    const float* a   = (const float*)d_in[3];
    float* out = (float*)d_out;

    cudaFuncSetAttribute(gat_main, cudaFuncAttributeMaxDynamicSharedMemorySize, SMEM_TOTAL);

    gat_prep<<<256, 256>>>(W, a);
    gat_prepB<<<1024, 256>>>(W);
    gat_main<<<dim3(2, 1024), NTHREADS, SMEM_TOTAL>>>(h, adj, out);
}

// round 11
// speedup vs baseline: 2.4827x; 1.1269x over previous
#include <cuda_runtime.h>
#include <cuda_fp16.h>
#include <math.h>
#include <stdint.h>

// Problem constants
#define BATCH   65536
#define NNODES  2
#define FIN     256
#define KDIM    1024
#define MROWS   131072
#define SLOPE   0.2f

// GEMM tiling
#define BM 128
#define BN 128
#define BK 64
#define NKITER 16               // 1024 / 64

// SMEM layout (bytes)
#define COEF   0                // 128 rows * 8 f32 = 4096
#define AOFF   4096             // A bufs: 2 * 36864 (hi 18432 + lo 18432)
#define ABUF   36864
#define SPLITO 18432            // lo offset within an A buf
#define BOFF   77824            // B bufs: 2 * 18432 (single fp16)
#define BBUF   18432
#define SMEM_TOTAL 114688
#define PITCH  144              // 64 fp16 = 128B data + 16B pad

#define NTHREADS 384            // warps 0-7 consumers, warps 8-11 producers

// Scratch: Wstack^T fp16, chunk-major [kc 0..15][n 0..255][64 fp16]
__device__ float g_wst[FIN * 8];
__device__ __half g_Wh[16 * 256 * 64];

__device__ __forceinline__ uint32_t smem_u32(const void* p) {
    uint32_t a;
    asm("{ .reg .u64 t; cvta.to.shared.u64 t, %1; cvt.u32.u64 %0, t; }" : "=r"(a) : "l"(p));
    return a;
}
__device__ __forceinline__ void ldsm_x4(uint32_t* r, uint32_t addr) {
    asm volatile("ldmatrix.sync.aligned.m8n8.x4.shared.b16 {%0,%1,%2,%3}, [%4];"
        : "=r"(r[0]), "=r"(r[1]), "=r"(r[2]), "=r"(r[3]) : "r"(addr));
}
__device__ __forceinline__ void mma_fp16(float* d, const uint32_t* a, const uint32_t* b) {
    asm volatile("mma.sync.aligned.m16n8k16.row.col.f32.f16.f16.f32 "
        "{%0,%1,%2,%3}, {%4,%5,%6,%7}, {%8,%9}, {%0,%1,%2,%3};"
        : "+f"(d[0]), "+f"(d[1]), "+f"(d[2]), "+f"(d[3])
        : "r"(a[0]), "r"(a[1]), "r"(a[2]), "r"(a[3]), "r"(b[0]), "r"(b[1]));
}
__device__ __forceinline__ void cp_async16(uint32_t daddr, const void* src) {
    asm volatile("cp.async.cg.shared.global [%0], [%1], 16;"
        :: "r"(daddr), "l"(src) : "memory");
}
__device__ __forceinline__ void cp_async_wait_all() {
    asm volatile("cp.async.wait_all;" ::: "memory");
}

// ---------------------------------------------------------------------------
// Kernel 1: wst dot products. One warp per output, 2048 outputs.
// ---------------------------------------------------------------------------
__global__ void gat_prep(const float* __restrict__ W, const float* __restrict__ a) {
    int wid = threadIdx.x >> 5, lane = threadIdx.x & 31;
    int t = blockIdx.x * 8 + wid;
    int f = t >> 3, c = t & 7, hd = c & 3, tg = c >> 2;
    const float4* wrow = (const float4*)(W + f * KDIM + hd * 256);
    const float4* av   = (const float4*)(a + hd * 512 + tg * 256);
    float s = 0.f;
#pragma unroll
    for (int q = 0; q < 2; ++q) {
        int i = lane + q * 32;
        float4 w4 = wrow[i], a4 = av[i];
        s += w4.x * a4.x + w4.y * a4.y + w4.z * a4.z + w4.w * a4.w;
    }
#pragma unroll
    for (int off = 16; off > 0; off >>= 1) s += __shfl_xor_sync(0xFFFFFFFFu, s, off);
    if (lane == 0) g_wst[t] = s;
}

// ---------------------------------------------------------------------------
// Kernel 1b: Wstack^T as single fp16, 64-wide chunk-major layout.
// Wt[n][k] = W[k&255][(k>>8)*256 + n]; dest = (k>>6)*16384 + n*64 + (k&63)
// ---------------------------------------------------------------------------
__global__ void gat_prepB(const float* __restrict__ W) {
    int idx = blockIdx.x * 256 + threadIdx.x;        // n*1024 + k
    int n = idx >> 10, k = idx & 1023;
    float w = W[(k & 255) * KDIM + (k >> 8) * 256 + n];
    g_Wh[(k >> 6) * 16384 + n * 64 + (k & 63)] = __float2half_rn(w);
}

// ---------------------------------------------------------------------------
// Kernel 2: warp-specialized GEMM (BK=64, fp16 2-term) + fused attention.
// ---------------------------------------------------------------------------
__device__ __forceinline__ float lrelu(float x) { return x > 0.f ? x : SLOPE * x; }

__device__ __forceinline__ void produce_chunk(
    char* smem, uint32_t sb, int c, int r, int n0g,
    const float* hp0, const float* hp1, const float2* coefp)
{
    const int buf = c & 1;

    // ---- B: cp.async GMEM -> SMEM (single fp16) ----
    {
        const uint32_t dbase = sb + BOFF + buf * BBUF;
        const char* srcH = (const char*)g_Wh + c * 32768 + n0g * 128;
#pragma unroll
        for (int g2 = 0; g2 < 8; ++g2) {
            int unit = r + 128 * g2;                 // 0..1023
            int n = unit >> 3, j = unit & 7;
            cp_async16(dbase + n * PITCH + j * 16, srcH + n * 128 + j * 16);
        }
    }

    // ---- A: build 64 k-values for row r, split into fp16 hi + fp16 lo ----
    const int hd = c >> 2;
    const int fo = (c & 3) * 64;
    float2 cc = coefp[hd];
    const float4* q0 = (const float4*)(hp0 + fo);
    const float4* q1 = (const float4*)(hp1 + fo);
    char* awh = smem + AOFF + buf * ABUF + r * PITCH;
    char* awl = awh + SPLITO;
#pragma unroll
    for (int s8 = 0; s8 < 8; ++s8) {                 // strips of 8 floats
        float4 a0 = q0[s8 * 2], a1 = q0[s8 * 2 + 1];
        float4 b0 = q1[s8 * 2], b1 = q1[s8 * 2 + 1];
        float x0 = cc.x * a0.x + cc.y * b0.x, x1 = cc.x * a0.y + cc.y * b0.y;
        float x2 = cc.x * a0.z + cc.y * b0.z, x3 = cc.x * a0.w + cc.y * b0.w;
        float x4 = cc.x * a1.x + cc.y * b1.x, x5 = cc.x * a1.y + cc.y * b1.y;
        float x6 = cc.x * a1.z + cc.y * b1.z, x7 = cc.x * a1.w + cc.y * b1.w;
        __half2 h01 = __floats2half2_rn(x0, x1);
        __half2 h23 = __floats2half2_rn(x2, x3);
        __half2 h45 = __floats2half2_rn(x4, x5);
        __half2 h67 = __floats2half2_rn(x6, x7);
        __half2 l01 = __floats2half2_rn(x0 - __low2float(h01), x1 - __high2float(h01));
        __half2 l23 = __floats2half2_rn(x2 - __low2float(h23), x3 - __high2float(h23));
        __half2 l45 = __floats2half2_rn(x4 - __low2float(h45), x5 - __high2float(h45));
        __half2 l67 = __floats2half2_rn(x6 - __low2float(h67), x7 - __high2float(h67));
        uint4 hv, lv;
        hv.x = *(uint32_t*)&h01; hv.y = *(uint32_t*)&h23;
        hv.z = *(uint32_t*)&h45; hv.w = *(uint32_t*)&h67;
        lv.x = *(uint32_t*)&l01; lv.y = *(uint32_t*)&l23;
        lv.z = *(uint32_t*)&l45; lv.w = *(uint32_t*)&l67;
        *(uint4*)(awh + s8 * 16) = hv;
        *(uint4*)(awl + s8 * 16) = lv;
    }
    cp_async_wait_all();                             // B granules landed
}

__global__ void __launch_bounds__(NTHREADS, 1)
gat_main(const float* __restrict__ h, const int* __restrict__ adj,
         float* __restrict__ out) {
    extern __shared__ char smem[];
    const uint32_t sb = smem_u32(smem);
    const int tid = threadIdx.x;
    const int wid = tid >> 5;
    const int lane = tid & 31;
    const int m0 = blockIdx.y * BM;
    const int n0g = blockIdx.x * BN;

    // ---- prologue: fused attention coefficients (warp per graph) ----
    for (int g = wid; g < 64; g += 12) {
        const float* hb = h + (size_t)((m0 >> 1) + g) * 512;
        float p[16];
#pragma unroll
        for (int c = 0; c < 16; ++c) p[c] = 0.f;
#pragma unroll
        for (int q = 0; q < 8; ++q) {
            int f = lane + q * 32;
            float h0 = hb[f];
            float h1 = hb[256 + f];
            const float4* wp = (const float4*)(g_wst + f * 8);
            float4 w0 = wp[0];
            float4 w1 = wp[1];
            p[0] += h0 * w0.x; p[1] += h0 * w0.y; p[2] += h0 * w0.z; p[3] += h0 * w0.w;
            p[4] += h0 * w1.x; p[5] += h0 * w1.y; p[6] += h0 * w1.z; p[7] += h0 * w1.w;
            p[8]  += h1 * w0.x; p[9]  += h1 * w0.y; p[10] += h1 * w0.z; p[11] += h1 * w0.w;
            p[12] += h1 * w1.x; p[13] += h1 * w1.y; p[14] += h1 * w1.z; p[15] += h1 * w1.w;
        }
#pragma unroll
        for (int off = 16; off > 0; off >>= 1) {
#pragma unroll
            for (int c = 0; c < 16; ++c) p[c] += __shfl_xor_sync(0xFFFFFFFFu, p[c], off);
        }
        if (lane == 0) {
            int b = (m0 >> 1) + g;
            int a00 = adj[b * 4 + 0], a01 = adj[b * 4 + 1];
            int a10 = adj[b * 4 + 2], a11 = adj[b * 4 + 3];
            float cf[16];
#pragma unroll
            for (int i = 0; i < 2; ++i) {
                int mk0 = (i == 0) ? a00 : a10;
                int mk1 = (i == 0) ? a01 : a11;
#pragma unroll
                for (int hd = 0; hd < 4; ++hd) {
                    float si = p[i * 8 + hd];
                    float e0 = lrelu(si + p[4 + hd]);
                    float e1 = lrelu(si + p[12 + hd]);
                    float mx = -INFINITY;
                    if (mk0) mx = e0;
                    if (mk1) mx = fmaxf(mx, e1);
                    float x0 = mk0 ? expf(e0 - mx) : 0.f;
                    float x1 = mk1 ? expf(e1 - mx) : 0.f;
                    float inv = 0.25f / (x0 + x1);
                    cf[i * 8 + hd * 2 + 0] = x0 * inv;
                    cf[i * 8 + hd * 2 + 1] = x1 * inv;
                }
            }
            float4* dst = (float4*)(smem + COEF + g * 64);
#pragma unroll
            for (int q = 0; q < 4; ++q) dst[q] = *(float4*)&cf[q * 4];
        }
    }
    __syncthreads();

    if (wid >= 8) {
        // ---------------- PRODUCER (warps 8-11) ----------------
        const int r = tid - 256;                     // 0..127
        const int row = m0 + r;
        const float* hp0 = h + (size_t)(row >> 1) * 512;
        const float* hp1 = hp0 + 256;
        const float2* coefp = (const float2*)(smem + COEF + r * 32);

        produce_chunk(smem, sb, 0, r, n0g, hp0, hp1, coefp);
        __syncthreads();                             // chunk 0 visible
        for (int c = 0; c < NKITER; ++c) {
            if (c + 1 < NKITER)
                produce_chunk(smem, sb, c + 1, r, n0g, hp0, hp1, coefp);
            __syncthreads();                         // chunk c+1 visible / buf c released
        }
    } else {
        // ---------------- CONSUMER (warps 0-7) ----------------
        const int mband = (wid & 3) * 32;
        const int nband = (wid >> 2) * 64;
        const uint32_t aoff_l = (uint32_t)((mband + (lane & 7) + ((lane >> 3) & 1) * 8) * PITCH
                                           + (lane >> 4) * 16);
        // B x4 covers n8 x k32: lane groups 0-7/8-15/16-23/24-31 -> k0-7/k8-15/k16-23/k24-31
        const uint32_t boff_l = (uint32_t)((nband + (lane & 7)) * PITCH + (lane >> 3) * 16);
        float acc[2][8][4];
#pragma unroll
        for (int mt = 0; mt < 2; ++mt)
#pragma unroll
            for (int nt = 0; nt < 8; ++nt)
#pragma unroll
                for (int e = 0; e < 4; ++e) acc[mt][nt][e] = 0.f;

        __syncthreads();                             // chunk 0 ready
        for (int c = 0; c < NKITER; ++c) {
            const int s = c & 1;
            const uint32_t ahb = sb + AOFF + s * ABUF + aoff_l;
            const uint32_t alb = ahb + SPLITO;
            const uint32_t bbb = sb + BOFF + s * BBUF + boff_l;
#pragma unroll
            for (int kg = 0; kg < 2; ++kg) {         // k32 groups
                uint32_t bb[8][4];
#pragma unroll
                for (int nt = 0; nt < 8; ++nt)
                    ldsm_x4(bb[nt], bbb + nt * 8 * PITCH + kg * 64);
#pragma unroll
                for (int sh = 0; sh < 2; ++sh) {     // k16 sub-slices
                    const int ks = kg * 2 + sh;
                    uint32_t ah[2][4], al[2][4];
                    ldsm_x4(ah[0], ahb + ks * 32);
                    ldsm_x4(ah[1], ahb + 16 * PITCH + ks * 32);
                    ldsm_x4(al[0], alb + ks * 32);
                    ldsm_x4(al[1], alb + 16 * PITCH + ks * 32);
                    // term-major: dependent MMAs on one accumulator are 16 apart
#pragma unroll
                    for (int mt = 0; mt < 2; ++mt)
#pragma unroll
                        for (int nt = 0; nt < 8; ++nt)
                            mma_fp16(acc[mt][nt], ah[mt], bb[nt] + 2 * sh);   // Ahi*B
#pragma unroll
                    for (int mt = 0; mt < 2; ++mt)
#pragma unroll
                        for (int nt = 0; nt < 8; ++nt)
                            mma_fp16(acc[mt][nt], al[mt], bb[nt] + 2 * sh);   // Alo*B
                }
            }
            __syncthreads();                         // next chunk ready / buf released
        }

        // ---- epilogue ----
        const int grow = m0 + mband + (lane >> 2);
        const int gcol = n0g + nband + (lane & 3) * 2;
#pragma unroll
        for (int mt = 0; mt < 2; ++mt) {
#pragma unroll
            for (int nt = 0; nt < 8; ++nt) {
                float* p = out + (size_t)(grow + mt * 16) * 256 + gcol + nt * 8;
                *(float2*)p = make_float2(acc[mt][nt][0], acc[mt][nt][1]);
                *(float2*)(p + 8 * 256) = make_float2(acc[mt][nt][2], acc[mt][nt][3]);
            }
        }
    }
}

// ---------------------------------------------------------------------------
// Launch
// ---------------------------------------------------------------------------
extern "C" void kernel_launch(void* const* d_in, const int* in_sizes, int n_in,
                              void* d_out, int out_size) {
    const float* h   = (const float*)d_in[0];
    const int*   adj = (const int*)  d_in[1];
    const float* W   = (const float*)d_in[2];
    const float* a   = (const float*)d_in[3];
    float* out = (float*)d_out;

    cudaFuncSetAttribute(gat_main, cudaFuncAttributeMaxDynamicSharedMemorySize, SMEM_TOTAL);

    gat_prep<<<256, 256>>>(W, a);
    gat_prepB<<<1024, 256>>>(W);
    gat_main<<<dim3(2, 1024), NTHREADS, SMEM_TOTAL>>>(h, adj, out);
}